// round 3
// baseline (speedup 1.0000x reference)
#include <cuda_runtime.h>

// PyramidROIAlign: B=2, N=1000 boxes, C=256, 7x7 pool.
// Phase A: per-BOX params (2000 threads). Phase B: gather/lerp with explicit MLP.

#define POOL 7
#define NPTS (POOL * POOL)
#define CCH 256
#define LANES 16
#define MAXB 8192   // >= B*N

// Per-box records (two 16B pieces for clean vector loads):
//   g_bf[bn] = {yH, ys, xH, xs}  with in_y = yH + ys*py, in_x = xH + xs*px
//   g_bp[bn] = {base byte addr of fmap[b], (W | Hm1<<32)}
__device__ float4     g_bf[MAXB];
__device__ ulonglong2 g_bp[MAXB];

__global__ void __launch_bounds__(256)
roi_boxparams_kernel(const float* __restrict__ boxes,
                     const float* __restrict__ image_shape,
                     const float* __restrict__ P2,
                     const float* __restrict__ P3,
                     const float* __restrict__ P4,
                     const float* __restrict__ P5,
                     int total_boxes, int boxes_per_batch)
{
    const int bn = blockIdx.x * blockDim.x + threadIdx.x;
    if (bn >= total_boxes) return;
    const int b = bn / boxes_per_batch;

    const float4 bx = ((const float4*)boxes)[bn];
    const float y1 = bx.x, x1 = bx.y, y2 = bx.z, x2 = bx.w;
    const float h = y2 - y1;
    const float w = x2 - x1;

    // Level selection — EXACT reference fp32 op order (discrete decision).
    const float area = image_shape[0] * image_shape[1];
    float lvlf = log2f(sqrtf(h * w) / (224.0f / sqrtf(area)));
    lvlf = fminf(5.0f, fmaxf(2.0f, 4.0f + rintf(lvlf)));
    const int lvl = (int)lvlf;

    const float* fmap;
    int H;
    if (lvl == 2)      { fmap = P2; H = 256; }
    else if (lvl == 3) { fmap = P3; H = 128; }
    else if (lvl == 4) { fmap = P4; H = 64;  }
    else               { fmap = P5; H = 32;  }
    const int W = H;
    const float Hm1f = (float)(H - 1);

    float4 f;
    f.x = y1 * Hm1f;              // yH
    f.y = h * Hm1f * (1.0f/6.0f); // ys
    f.z = x1 * Hm1f;              // xH
    f.w = w * Hm1f * (1.0f/6.0f); // xs
    g_bf[bn] = f;

    ulonglong2 p;
    p.x = (unsigned long long)fmap +
          (unsigned long long)b * H * W * CCH * sizeof(float);
    p.y = (unsigned long long)(unsigned)W |
          ((unsigned long long)(unsigned)(H - 1) << 32);
    g_bp[bn] = p;
}

__global__ void __launch_bounds__(256)
roi_gather_kernel(float* __restrict__ out, int total_items)
{
    const long long g = (long long)blockIdx.x * blockDim.x + threadIdx.x;
    const int item = (int)(g >> 4);
    const int lane = (int)(g & (LANES - 1));
    if (item >= total_items) return;

    const int bn = item / NPTS;
    const int pt = item - bn * NPTS;
    const int py = pt / POOL;
    const int px = pt - py * POOL;

    const float4     f = g_bf[bn];   // L1-resident broadcast
    const ulonglong2 p = g_bp[bn];
    const int W   = (int)(p.y & 0xffffffffull);
    const int Hm1 = (int)(p.y >> 32);

    const float in_y = f.x + f.y * (float)py;
    const float in_x = f.z + f.w * (float)px;
    const float y0f = floorf(in_y);
    const float x0f = floorf(in_x);
    const float wy = in_y - y0f;
    const float wx = in_x - x0f;

    int y0  = min(max((int)y0f, 0), Hm1);
    int y1i = min(y0 + 1, Hm1);
    int x0  = min(max((int)x0f, 0), Hm1);   // square maps: Wm1 == Hm1
    int x1i = min(x0 + 1, Hm1);

    const float4* base4 = (const float4*)p.x;
    const int C4 = CCH / 4;
    const float4* __restrict__ rT = base4 + (size_t)(y0  * W) * C4;
    const float4* __restrict__ rB = base4 + (size_t)(y1i * W) * C4;
    const float4* __restrict__ tl = rT + (size_t)x0  * C4;
    const float4* __restrict__ tr = rT + (size_t)x1i * C4;
    const float4* __restrict__ bl = rB + (size_t)x0  * C4;
    const float4* __restrict__ br = rB + (size_t)x1i * C4;
    float4* __restrict__ o = (float4*)(out + (size_t)item * CCH);

#pragma unroll
    for (int half = 0; half < 2; half++) {
        const int c0 = lane + (2 * half) * LANES;
        const int c1 = c0 + LANES;
        // 8 independent loads in flight per batch
        const float4 tl0 = tl[c0], tr0 = tr[c0], bl0 = bl[c0], br0 = br[c0];
        const float4 tl1 = tl[c1], tr1 = tr[c1], bl1 = bl[c1], br1 = br[c1];

        float4 r0, r1;
        float t, bt;
        t  = tl0.x + (tr0.x - tl0.x) * wx;  bt = bl0.x + (br0.x - bl0.x) * wx;  r0.x = t + (bt - t) * wy;
        t  = tl0.y + (tr0.y - tl0.y) * wx;  bt = bl0.y + (br0.y - bl0.y) * wx;  r0.y = t + (bt - t) * wy;
        t  = tl0.z + (tr0.z - tl0.z) * wx;  bt = bl0.z + (br0.z - bl0.z) * wx;  r0.z = t + (bt - t) * wy;
        t  = tl0.w + (tr0.w - tl0.w) * wx;  bt = bl0.w + (br0.w - bl0.w) * wx;  r0.w = t + (bt - t) * wy;
        t  = tl1.x + (tr1.x - tl1.x) * wx;  bt = bl1.x + (br1.x - bl1.x) * wx;  r1.x = t + (bt - t) * wy;
        t  = tl1.y + (tr1.y - tl1.y) * wx;  bt = bl1.y + (br1.y - bl1.y) * wx;  r1.y = t + (bt - t) * wy;
        t  = tl1.z + (tr1.z - tl1.z) * wx;  bt = bl1.z + (br1.z - bl1.z) * wx;  r1.z = t + (bt - t) * wy;
        t  = tl1.w + (tr1.w - tl1.w) * wx;  bt = bl1.w + (br1.w - bl1.w) * wx;  r1.w = t + (bt - t) * wy;

        // streaming stores: never re-read, keep L2 for fmap
        __stcs(&o[c0], r0);
        __stcs(&o[c1], r1);
    }
}

extern "C" void kernel_launch(void* const* d_in, const int* in_sizes, int n_in,
                              void* d_out, int out_size)
{
    const float* boxes = (const float*)d_in[0];
    const float* ishp  = (const float*)d_in[1];
    const float* P2    = (const float*)d_in[2];
    const float* P3    = (const float*)d_in[3];
    const float* P4    = (const float*)d_in[4];
    const float* P5    = (const float*)d_in[5];
    float* out = (float*)d_out;

    const int B = in_sizes[2] / (256 * 256 * 256);
    const int total_boxes = in_sizes[0] / 4;
    const int boxes_per_batch = total_boxes / B;
    const int total_items = total_boxes * NPTS;

    roi_boxparams_kernel<<<(total_boxes + 255) / 256, 256>>>(
        boxes, ishp, P2, P3, P4, P5, total_boxes, boxes_per_batch);

    const long long total_threads = (long long)total_items * LANES;
    roi_gather_kernel<<<(int)((total_threads + 255) / 256), 256>>>(out, total_items);
}

// round 5
// speedup vs baseline: 1.2872x; 1.2872x over previous
#include <cuda_runtime.h>

// PyramidROIAlign: B=2, N=1000 boxes, C=256, 7x7 pool.
// Phase A: one WARP per box, two passes over the 49 items (lane, lane+32).
// Phase B: gather/lerp, 16 lanes/item, 2 batches of 8 independent LDG.128.

#define POOL 7
#define NPTS (POOL * POOL)
#define CCH 256
#define LANES 16
#define MAX_ITEMS (131072)   // >= B*N*49

__device__ ulonglong4 g_addr[MAX_ITEMS];   // tl, tr, bl, br absolute byte addresses
__device__ float2     g_w[MAX_ITEMS];      // wx, wy

__global__ void __launch_bounds__(256)
roi_params_kernel(const float* __restrict__ boxes,
                  const float* __restrict__ image_shape,
                  const float* __restrict__ P2,
                  const float* __restrict__ P3,
                  const float* __restrict__ P4,
                  const float* __restrict__ P5,
                  int total_boxes, int boxes_per_batch)
{
    const int gw = (blockIdx.x * blockDim.x + threadIdx.x) >> 5;  // box index
    const int lane = threadIdx.x & 31;
    if (gw >= total_boxes) return;

    const int b = gw / boxes_per_batch;
    const float4 bx = ((const float4*)boxes)[gw];
    const float y1 = bx.x, x1 = bx.y, y2 = bx.z, x2 = bx.w;
    const float h = y2 - y1;
    const float w = x2 - x1;

    // Level selection — exact reference fp32 op order; rintf == jnp.round.
    const float area = image_shape[0] * image_shape[1];
    float lvlf = log2f(sqrtf(h * w) / (224.0f / sqrtf(area)));
    lvlf = fminf(5.0f, fmaxf(2.0f, 4.0f + rintf(lvlf)));
    const int lvl = (int)lvlf;

    const float* fmap;
    int H;
    if (lvl == 2)      { fmap = P2; H = 256; }
    else if (lvl == 3) { fmap = P3; H = 128; }
    else if (lvl == 4) { fmap = P4; H = 64;  }
    else               { fmap = P5; H = 32;  }
    const int W = H;
    const float Hm1f = (float)(H - 1);

    const unsigned long long base =
        (unsigned long long)fmap + (unsigned long long)b * H * W * CCH * 4ull;

    // Two passes cover the 49 items with one 32-lane warp.
#pragma unroll
    for (int pass = 0; pass < 2; pass++) {
        const int pt = lane + pass * 32;
        if (pt >= NPTS) break;
        const int py = pt / POOL;
        const int px = pt - py * POOL;

        // Reference order: in_y = (y1 + h*gy) * (H-1)
        const float gy = (float)py * (1.0f / 6.0f);
        const float gx = (float)px * (1.0f / 6.0f);
        const float in_y = (y1 + h * gy) * Hm1f;
        const float in_x = (x1 + w * gx) * Hm1f;

        const float y0f = floorf(in_y);
        const float x0f = floorf(in_x);
        const float wy = in_y - y0f;
        const float wx = in_x - x0f;

        int y0  = min(max((int)y0f, 0), H - 1);
        int y1i = min(y0 + 1, H - 1);
        int x0  = min(max((int)x0f, 0), W - 1);
        int x1i = min(x0 + 1, W - 1);

        const unsigned long long rowT = base + (unsigned long long)(y0  * W) * (CCH * 4ull);
        const unsigned long long rowB = base + (unsigned long long)(y1i * W) * (CCH * 4ull);

        const int item = gw * NPTS + pt;
        ulonglong4 a;
        a.x = rowT + (unsigned long long)x0  * (CCH * 4ull);
        a.y = rowT + (unsigned long long)x1i * (CCH * 4ull);
        a.z = rowB + (unsigned long long)x0  * (CCH * 4ull);
        a.w = rowB + (unsigned long long)x1i * (CCH * 4ull);
        g_addr[item] = a;
        g_w[item] = make_float2(wx, wy);
    }
}

__global__ void __launch_bounds__(256)
roi_gather_kernel(float* __restrict__ out, int total_items)
{
    const long long g = (long long)blockIdx.x * blockDim.x + threadIdx.x;
    const int item = (int)(g >> 4);
    const int lane = (int)(g & (LANES - 1));
    if (item >= total_items) return;

    const ulonglong4 a = g_addr[item];
    const float2 wv = g_w[item];
    const float wx = wv.x, wy = wv.y;

    const float4* __restrict__ tl = (const float4*)a.x;
    const float4* __restrict__ tr = (const float4*)a.y;
    const float4* __restrict__ bl = (const float4*)a.z;
    const float4* __restrict__ br = (const float4*)a.w;
    float4* __restrict__ o = (float4*)(out + (size_t)item * CCH);

#pragma unroll
    for (int half = 0; half < 2; half++) {
        const int c0 = lane + (2 * half) * LANES;
        const int c1 = c0 + LANES;

        // 8 independent LDG.128 in flight before any dependent math.
        float4 v[8];
        v[0] = __ldg(tl + c0);
        v[1] = __ldg(tr + c0);
        v[2] = __ldg(bl + c0);
        v[3] = __ldg(br + c0);
        v[4] = __ldg(tl + c1);
        v[5] = __ldg(tr + c1);
        v[6] = __ldg(bl + c1);
        v[7] = __ldg(br + c1);

        float4 r0, r1;
        float t, bt;
        t  = v[0].x + (v[1].x - v[0].x) * wx;  bt = v[2].x + (v[3].x - v[2].x) * wx;  r0.x = t + (bt - t) * wy;
        t  = v[0].y + (v[1].y - v[0].y) * wx;  bt = v[2].y + (v[3].y - v[2].y) * wx;  r0.y = t + (bt - t) * wy;
        t  = v[0].z + (v[1].z - v[0].z) * wx;  bt = v[2].z + (v[3].z - v[2].z) * wx;  r0.z = t + (bt - t) * wy;
        t  = v[0].w + (v[1].w - v[0].w) * wx;  bt = v[2].w + (v[3].w - v[2].w) * wx;  r0.w = t + (bt - t) * wy;
        t  = v[4].x + (v[5].x - v[4].x) * wx;  bt = v[6].x + (v[7].x - v[6].x) * wx;  r1.x = t + (bt - t) * wy;
        t  = v[4].y + (v[5].y - v[4].y) * wx;  bt = v[6].y + (v[7].y - v[6].y) * wx;  r1.y = t + (bt - t) * wy;
        t  = v[4].z + (v[5].z - v[4].z) * wx;  bt = v[6].z + (v[7].z - v[6].z) * wx;  r1.z = t + (bt - t) * wy;
        t  = v[4].w + (v[5].w - v[4].w) * wx;  bt = v[6].w + (v[7].w - v[6].w) * wx;  r1.w = t + (bt - t) * wy;

        o[c0] = r0;
        o[c1] = r1;
    }
}

extern "C" void kernel_launch(void* const* d_in, const int* in_sizes, int n_in,
                              void* d_out, int out_size)
{
    const float* boxes = (const float*)d_in[0];
    const float* ishp  = (const float*)d_in[1];
    const float* P2    = (const float*)d_in[2];
    const float* P3    = (const float*)d_in[3];
    const float* P4    = (const float*)d_in[4];
    const float* P5    = (const float*)d_in[5];
    float* out = (float*)d_out;

    const int B = in_sizes[2] / (256 * 256 * 256);
    const int total_boxes = in_sizes[0] / 4;
    const int boxes_per_batch = total_boxes / B;
    const int total_items = total_boxes * NPTS;

    // One warp per box.
    {
        const long long t = (long long)total_boxes * 32;
        roi_params_kernel<<<(int)((t + 255) / 256), 256>>>(
            boxes, ishp, P2, P3, P4, P5, total_boxes, boxes_per_batch);
    }
    {
        const long long t = (long long)total_items * LANES;
        roi_gather_kernel<<<(int)((t + 255) / 256), 256>>>(out, total_items);
    }
}

// round 6
// speedup vs baseline: 1.3791x; 1.0714x over previous
#include <cuda_runtime.h>

// PyramidROIAlign: B=2, N=1000 boxes, C=256, 7x7 pool. Single fused kernel.
// Each 256-thread CTA handles 16 items: threads 0..15 compute per-item params
// (corner addresses + weights) into SMEM, then all threads gather/lerp.

#define POOL 7
#define NPTS (POOL * POOL)
#define CCH 256
#define LANES 16
#define ITEMS_PER_CTA 16

__global__ void __launch_bounds__(256)
roi_fused_kernel(const float* __restrict__ boxes,
                 const float* __restrict__ image_shape,
                 const float* __restrict__ P2,
                 const float* __restrict__ P3,
                 const float* __restrict__ P4,
                 const float* __restrict__ P5,
                 float* __restrict__ out,
                 int total_items, int boxes_per_batch)
{
    __shared__ ulonglong4 s_addr[ITEMS_PER_CTA];
    __shared__ float2     s_w[ITEMS_PER_CTA];

    const int item_base = blockIdx.x * ITEMS_PER_CTA;
    const int tid = threadIdx.x;

    if (tid < ITEMS_PER_CTA) {
        const int item = item_base + tid;
        if (item < total_items) {
            const int bn = item / NPTS;
            const int pt = item - bn * NPTS;
            const int py = pt / POOL;
            const int px = pt - py * POOL;
            const int b  = bn / boxes_per_batch;

            const float4 bx = ((const float4*)boxes)[bn];
            const float y1 = bx.x, x1 = bx.y, y2 = bx.z, x2 = bx.w;
            const float h = y2 - y1;
            const float w = x2 - x1;

            // Level selection — exact reference fp32 op order; rintf == jnp.round.
            const float area = image_shape[0] * image_shape[1];
            float lvlf = log2f(sqrtf(h * w) / (224.0f / sqrtf(area)));
            lvlf = fminf(5.0f, fmaxf(2.0f, 4.0f + rintf(lvlf)));
            const int lvl = (int)lvlf;

            const float* fmap;
            int H;
            if (lvl == 2)      { fmap = P2; H = 256; }
            else if (lvl == 3) { fmap = P3; H = 128; }
            else if (lvl == 4) { fmap = P4; H = 64;  }
            else               { fmap = P5; H = 32;  }
            const int W = H;

            // Reference order: in_y = (y1 + h*gy) * (H-1)
            const float gy = (float)py * (1.0f / 6.0f);
            const float gx = (float)px * (1.0f / 6.0f);
            const float in_y = (y1 + h * gy) * (float)(H - 1);
            const float in_x = (x1 + w * gx) * (float)(W - 1);

            const float y0f = floorf(in_y);
            const float x0f = floorf(in_x);
            const float wy = in_y - y0f;
            const float wx = in_x - x0f;

            int y0  = min(max((int)y0f, 0), H - 1);
            int y1i = min(y0 + 1, H - 1);
            int x0  = min(max((int)x0f, 0), W - 1);
            int x1i = min(x0 + 1, W - 1);

            const unsigned long long base =
                (unsigned long long)fmap + (unsigned long long)b * H * W * CCH * 4ull;
            const unsigned long long rowT = base + (unsigned long long)(y0  * W) * (CCH * 4ull);
            const unsigned long long rowB = base + (unsigned long long)(y1i * W) * (CCH * 4ull);

            ulonglong4 a;
            a.x = rowT + (unsigned long long)x0  * (CCH * 4ull);
            a.y = rowT + (unsigned long long)x1i * (CCH * 4ull);
            a.z = rowB + (unsigned long long)x0  * (CCH * 4ull);
            a.w = rowB + (unsigned long long)x1i * (CCH * 4ull);
            s_addr[tid] = a;
            s_w[tid] = make_float2(wx, wy);
        }
    }
    __syncthreads();

    const int local = tid >> 4;            // item within CTA
    const int lane  = tid & (LANES - 1);   // float4 lane group
    const int item = item_base + local;
    if (item >= total_items) return;

    const ulonglong4 a = s_addr[local];    // SMEM broadcast
    const float2 wv = s_w[local];
    const float wx = wv.x, wy = wv.y;

    const float4* __restrict__ tl = (const float4*)a.x;
    const float4* __restrict__ tr = (const float4*)a.y;
    const float4* __restrict__ bl = (const float4*)a.z;
    const float4* __restrict__ br = (const float4*)a.w;
    float4* __restrict__ o = (float4*)(out + (size_t)item * CCH);

#pragma unroll
    for (int j = 0; j < 4; j++) {
        const int c = lane + j * LANES;
        const float4 vtl = tl[c];
        const float4 vtr = tr[c];
        const float4 vbl = bl[c];
        const float4 vbr = br[c];
        float4 r;
        float t, bt;
        t  = vtl.x + (vtr.x - vtl.x) * wx;  bt = vbl.x + (vbr.x - vbl.x) * wx;  r.x = t + (bt - t) * wy;
        t  = vtl.y + (vtr.y - vtl.y) * wx;  bt = vbl.y + (vbr.y - vbl.y) * wx;  r.y = t + (bt - t) * wy;
        t  = vtl.z + (vtr.z - vtl.z) * wx;  bt = vbl.z + (vbr.z - vbl.z) * wx;  r.z = t + (bt - t) * wy;
        t  = vtl.w + (vtr.w - vtl.w) * wx;  bt = vbl.w + (vbr.w - vbl.w) * wx;  r.w = t + (bt - t) * wy;
        o[c] = r;
    }
}

extern "C" void kernel_launch(void* const* d_in, const int* in_sizes, int n_in,
                              void* d_out, int out_size)
{
    const float* boxes = (const float*)d_in[0];
    const float* ishp  = (const float*)d_in[1];
    const float* P2    = (const float*)d_in[2];
    const float* P3    = (const float*)d_in[3];
    const float* P4    = (const float*)d_in[4];
    const float* P5    = (const float*)d_in[5];
    float* out = (float*)d_out;

    const int B = in_sizes[2] / (256 * 256 * 256);
    const int total_boxes = in_sizes[0] / 4;
    const int boxes_per_batch = total_boxes / B;
    const int total_items = total_boxes * NPTS;

    const int blocks = (total_items + ITEMS_PER_CTA - 1) / ITEMS_PER_CTA;
    roi_fused_kernel<<<blocks, 256>>>(boxes, ishp, P2, P3, P4, P5, out,
                                      total_items, boxes_per_batch);
}